// round 15
// baseline (speedup 1.0000x reference)
#include <cuda_runtime.h>
#include <cuda_fp16.h>
#include <cstdint>

#define BT   4096
#define HDIM 2048
#define VDIM 32000
#define KC1H (HDIM / 16)           // 128 k16-chunks (gemm1)
#define KC2H (VDIM / 16)           // 2000 k16-chunks (gemm2)
#define SPLIT 4
#define NZSL 500                   // 250 n-tiles * 2 wn

// Output layout: [loss(1) | logits(BT*V) | lse(BT) | ntl(BT) | grad_x(BT*H)]
#define OUT_LOSS   0
#define OUT_LOGITS 1LL
#define OUT_LSE    (1LL + (long long)BT * VDIM)
#define OUT_NTL    (OUT_LSE + BT)
#define OUT_GRADX  (OUT_NTL + BT)

// Geometry: CTA 128x128, BK=32 (2 k16), 128 thr, 4 warps (2m x 2n), warp 64x64
#define BM 128
#define BN 128
#define STG_AW 2048                // A: 8 m16 * 2 kc * 128 words
#define STG_W  4096                // + B: 8 n16 * 2 kc * 128 words
#define G_SMEM 65536               // 4 stages

// ---- scratch (fp16 fragment-major) ----
// A unit [m16][k16]: lane-> uint4 {(g,2tg|+1),(g+8,..),(g,2tg+8|+9),(g+8,..)}
// B unit [n16][k16]: lane-> uint4 {f0.b0, f0.b1, f1.b0, f1.b1}
__device__ uint32_t g_xt   [(size_t)(BT / 16) * KC1H * 128];
__device__ uint32_t g_wt   [(size_t)(VDIM / 16) * KC1H * 128];  // (n=v,k=h)
__device__ uint32_t g_wt2  [(size_t)(HDIM / 16) * KC2H * 128];  // (n=h,k=v)
__device__ uint32_t g_probs[(size_t)(BT / 16) * KC2H * 128];
__device__ float    g_gpart[(size_t)SPLIT * BT * HDIM];
__device__ float    g_zpart[(size_t)BT * NZSL];                 // [row][slice]
__device__ float    g_scale[BT];

__device__ __forceinline__ uint32_t packh2(float lo, float hi) {
    __half2 h = __floats2half2_rn(lo, hi);
    return *(uint32_t*)&h;
}
__device__ __forceinline__ void mma16(float* d, const uint32_t* a, const uint32_t* b) {
    asm volatile(
        "mma.sync.aligned.m16n8k16.row.col.f32.f16.f16.f32 "
        "{%0,%1,%2,%3}, {%4,%5,%6,%7}, {%8,%9}, {%0,%1,%2,%3};\n"
        : "+f"(d[0]), "+f"(d[1]), "+f"(d[2]), "+f"(d[3])
        : "r"(a[0]), "r"(a[1]), "r"(a[2]), "r"(a[3]),
          "r"(b[0]), "r"(b[1]));
}
__device__ __forceinline__ void cpa16(uint32_t smem, const void* gmem) {
    asm volatile("cp.async.cg.shared.global [%0], [%1], 16;\n" :: "r"(smem), "l"(gmem));
}
__device__ __forceinline__ void cpa_commit() {
    asm volatile("cp.async.commit_group;\n" ::: "memory");
}
__device__ __forceinline__ void cpa_wait0() {
    asm volatile("cp.async.wait_group 0;\n" ::: "memory");
}
__device__ __forceinline__ void cpa_wait1() {
    asm volatile("cp.async.wait_group 1;\n" ::: "memory");
}
__device__ __forceinline__ void cpa_wait2() {
    asm volatile("cp.async.wait_group 2;\n" ::: "memory");
}

// ---------------------------------------------------------------------------
// Converters into fp16 fragment-major layouts
// ---------------------------------------------------------------------------
__global__ void convA_kernel(const float* __restrict__ x)
{
    const int lane = threadIdx.x & 31;
    const int g = lane >> 2, tg = lane & 3;
    const int warp = (blockIdx.x * blockDim.x + threadIdx.x) >> 5;
    const int nwarp = (gridDim.x * blockDim.x) >> 5;
    const int NF = (BT / 16) * KC1H;                 // 32768
    for (int f = warp; f < NF; f += nwarp) {
        int m16 = f >> 7, kc = f & (KC1H - 1);
        const float* p = x + (size_t)(m16 * 16 + g) * HDIM + kc * 16;
        uint4 o;
        o.x = packh2(p[2 * tg],            p[2 * tg + 1]);
        o.y = packh2(p[8 * HDIM + 2 * tg], p[8 * HDIM + 2 * tg + 1]);
        o.z = packh2(p[2 * tg + 8],        p[2 * tg + 9]);
        o.w = packh2(p[8 * HDIM + 2 * tg + 8], p[8 * HDIM + 2 * tg + 9]);
        *(uint4*)(g_xt + (size_t)f * 128 + lane * 4) = o;
    }
}
// One pass over w: stage 64x64 tile, emit BOTH g_wt (n16=v,k=h) and g_wt2 (n16=h,k=v)
__global__ void convB_kernel(const float* __restrict__ w)
{
    __shared__ float t[64][68];
    const int v0 = blockIdx.x * 64;      // 500
    const int h0 = blockIdx.y * 64;      // 32
    const int tid = threadIdx.x;         // 256
    #pragma unroll
    for (int i = 0; i < 4; i++) {
        int q = tid + i * 256;           // 1024 float4 chunks
        int r = q >> 4, c4 = q & 15;
        float4 v = *(const float4*)(w + (size_t)(v0 + r) * HDIM + h0 + c4 * 4);
        t[r][c4 * 4 + 0] = v.x; t[r][c4 * 4 + 1] = v.y;
        t[r][c4 * 4 + 2] = v.z; t[r][c4 * 4 + 3] = v.w;
    }
    __syncthreads();
    const int lane = tid & 31, wid = tid >> 5;
    const int g = lane >> 2, tg = lane & 3;
    if (wid < 4) {
        #pragma unroll
        for (int kj = 0; kj < 4; kj++) {
            const float* ra = &t[wid * 16 + g][kj * 16];
            const float* rb = &t[wid * 16 + 8 + g][kj * 16];
            uint4 o;
            o.x = packh2(ra[2 * tg],     ra[2 * tg + 1]);
            o.y = packh2(ra[2 * tg + 8], ra[2 * tg + 9]);
            o.z = packh2(rb[2 * tg],     rb[2 * tg + 1]);
            o.w = packh2(rb[2 * tg + 8], rb[2 * tg + 9]);
            *(uint4*)(g_wt + ((size_t)(v0 / 16 + wid) * KC1H + h0 / 16 + kj) * 128
                      + lane * 4) = o;
        }
    } else {
        const int wp = wid - 4;
        #pragma unroll
        for (int kj = 0; kj < 4; kj++) {
            int vb = kj * 16;
            int ca = wp * 16 + g, cb = wp * 16 + 8 + g;
            uint4 o;
            o.x = packh2(t[vb + 2 * tg][ca],     t[vb + 2 * tg + 1][ca]);
            o.y = packh2(t[vb + 2 * tg + 8][ca], t[vb + 2 * tg + 9][ca]);
            o.z = packh2(t[vb + 2 * tg][cb],     t[vb + 2 * tg + 1][cb]);
            o.w = packh2(t[vb + 2 * tg + 8][cb], t[vb + 2 * tg + 9][cb]);
            *(uint4*)(g_wt2 + ((size_t)(h0 / 16 + wp) * KC2H + v0 / 16 + kj) * 128
                      + lane * 4) = o;
        }
    }
}

// ---------------------------------------------------------------------------
// mainloop pieces: 128x128 CTA, warp 64x64, BK=32 (2 k16), 4-stage, dist-3
// ---------------------------------------------------------------------------
#define GEMM_DECLS                                            \
    const int tid  = threadIdx.x;                             \
    const int lane = tid & 31;                                \
    const int wid  = tid >> 5;                                \
    const int g    = lane >> 2;                               \
    const int tg   = lane & 3;                                \
    const int wm   = wid & 1;                                 \
    const int wn   = wid >> 1;                                \
    float acc[4][8][4];                                       \
    _Pragma("unroll")                                         \
    for (int i = 0; i < 4; i++)                               \
        _Pragma("unroll")                                     \
        for (int j = 0; j < 8; j++)                           \
            _Pragma("unroll")                                 \
            for (int q = 0; q < 4; q++) acc[i][j][q] = 0.f;

#define GEMM_ISSUE(AG, BG, KCD)                                               \
    auto issue = [&](int kt) {                                                \
        const uint32_t sb = smb + (uint32_t)(kt & 3) * (STG_W * 4);           \
        const int kc0 = kt * 2;                                              \
        _Pragma("unroll")                                                     \
        for (int i = 0; i < 4; i++) {             /* A: 512 chunks */         \
            int q = tid + i * 128;                                            \
            int ai = q >> 6, rem = q & 63;                                    \
            int kcl = rem >> 5, c = rem & 31;                                 \
            cpa16(sb + (ai * 256 + kcl * 128 + c * 4) * 4,                    \
                  AG + ((size_t)(m0 / 16 + ai) * KCD + kc0 + kcl) * 128 + c * 4); \
        }                                                                     \
        _Pragma("unroll")                                                     \
        for (int i = 0; i < 4; i++) {             /* B: 512 chunks */         \
            int q = tid + i * 128;                                            \
            int bj = q >> 6, rem = q & 63;                                    \
            int kcl = rem >> 5, c = rem & 31;                                 \
            cpa16(sb + (STG_AW + bj * 256 + kcl * 128 + c * 4) * 4,           \
                  BG + ((size_t)(n0 / 16 + bj) * KCD + kc0 + kcl) * 128 + c * 4); \
        }                                                                     \
        cpa_commit();                                                         \
    };

#define GEMM_COMPUTE(kt)                                                      \
    {                                                                         \
        const uint32_t* Aw = sm + (kt & 3) * STG_W;                           \
        const uint32_t* Bw = Aw + STG_AW;                                     \
        _Pragma("unroll")                                                     \
        for (int kc = 0; kc < 2; kc++) {                                      \
            uint4 av[4];                                                      \
            _Pragma("unroll")                                                 \
            for (int mt = 0; mt < 4; mt++)                                    \
                av[mt] = *(const uint4*)(Aw + (wm * 4 + mt) * 256 + kc * 128 + lane * 4); \
            _Pragma("unroll")                                                 \
            for (int nt16 = 0; nt16 < 4; nt16++) {                            \
                uint4 bv = *(const uint4*)(Bw + (wn * 4 + nt16) * 256 + kc * 128 + lane * 4); \
                _Pragma("unroll")                                             \
                for (int mt = 0; mt < 4; mt++) {                              \
                    mma16(acc[mt][2 * nt16],     (const uint32_t*)&av[mt], &bv.x); \
                    mma16(acc[mt][2 * nt16 + 1], (const uint32_t*)&av[mt], &bv.z); \
                }                                                             \
            }                                                                 \
        }                                                                     \
    }

// pending groups at top of iter kt: {kt .. min(kt+2, kend-1)}
#define GEMM_WAIT(kt, kend)                                   \
    if ((kend) - (kt) >= 3)      cpa_wait2();                 \
    else if ((kend) - (kt) == 2) cpa_wait1();                 \
    else                         cpa_wait0();

// ---------------------------------------------------------------------------
// Phase 1: logits = x @ w^T. Pure register epilogue: z partials, logits
// (scalar stores, sector-dense), probs (uint4 units straight from fragments).
// ---------------------------------------------------------------------------
__global__ __launch_bounds__(128, 2) void gemm1_kernel(float* __restrict__ out)
{
    extern __shared__ uint32_t sm[];
    const uint32_t smb = (uint32_t)__cvta_generic_to_shared(sm);
    GEMM_DECLS
    const int m0 = blockIdx.x * BM;
    const int n0 = blockIdx.y * BN;
    GEMM_ISSUE(g_xt, g_wt, KC1H)

    issue(0); issue(1); issue(2);
    const int NK = HDIM / 32;   // 64
    for (int kt = 0; kt < NK; kt++) {
        GEMM_WAIT(kt, NK)
        __syncthreads();
        if (kt + 3 < NK) issue(kt + 3);
        GEMM_COMPUTE(kt)
    }

    // ---- z partials straight from fragments ([row][slice] layout) ----
    {
        const int slice = blockIdx.y * 2 + wn;
        #pragma unroll
        for (int mt = 0; mt < 4; mt++) {
            float s0 = 0.f, s1 = 0.f;
            #pragma unroll
            for (int nt = 0; nt < 8; nt++) {
                s0 += __expf(acc[mt][nt][0]) + __expf(acc[mt][nt][1]);
                s1 += __expf(acc[mt][nt][2]) + __expf(acc[mt][nt][3]);
            }
            s0 += __shfl_xor_sync(0xFFFFFFFFu, s0, 1);
            s0 += __shfl_xor_sync(0xFFFFFFFFu, s0, 2);
            s1 += __shfl_xor_sync(0xFFFFFFFFu, s1, 1);
            s1 += __shfl_xor_sync(0xFFFFFFFFu, s1, 2);
            if (tg == 0) {
                int r = m0 + wm * 64 + mt * 16 + g;
                g_zpart[(size_t)r * NZSL + slice]       = s0;
                g_zpart[(size_t)(r + 8) * NZSL + slice] = s1;
            }
        }
    }

    // ---- logits: direct scalar stores (out+1 is 4B-aligned only) ----
    float* outL = out + OUT_LOGITS;
    #pragma unroll
    for (int mt = 0; mt < 4; mt++) {
        #pragma unroll
        for (int nt = 0; nt < 8; nt++) {
            int r = m0 + wm * 64 + mt * 16 + g;
            int c = n0 + wn * 64 + nt * 8 + tg * 2;
            outL[(size_t)r * VDIM + c]           = acc[mt][nt][0];
            outL[(size_t)r * VDIM + c + 1]       = acc[mt][nt][1];
            outL[(size_t)(r + 8) * VDIM + c]     = acc[mt][nt][2];
            outL[(size_t)(r + 8) * VDIM + c + 1] = acc[mt][nt][3];
        }
    }

    // ---- probs: A-perm units straight from fragments ----
    // unit (m16 = m0/16 + wm*4 + mt, kchunk = (n0 + wn*64)/16 + j), lane offset lane*4
    #pragma unroll
    for (int mt = 0; mt < 4; mt++) {
        #pragma unroll
        for (int j = 0; j < 4; j++) {
            uint4 o;
            o.x = packh2(__expf(acc[mt][2 * j][0]),     __expf(acc[mt][2 * j][1]));
            o.y = packh2(__expf(acc[mt][2 * j][2]),     __expf(acc[mt][2 * j][3]));
            o.z = packh2(__expf(acc[mt][2 * j + 1][0]), __expf(acc[mt][2 * j + 1][1]));
            o.w = packh2(__expf(acc[mt][2 * j + 1][2]), __expf(acc[mt][2 * j + 1][3]));
            *(uint4*)(g_probs + ((size_t)(m0 / 16 + wm * 4 + mt) * KC2H
                                 + (n0 + wn * 64) / 16 + j) * 128 + lane * 4) = o;
        }
    }
}

// ---------------------------------------------------------------------------
// Phase 2: zred — Z, lse, 1/Z, ntl. Target dtype runtime-detected
// (JAX x64-off downcasts int64 -> int32; odd words all-zero => int64).
// ---------------------------------------------------------------------------
__global__ void zred_kernel(const void* __restrict__ target,
                            float* __restrict__ out)
{
    __shared__ int oddor;
    const int tid = threadIdx.x;
    const int lane = tid & 31;
    const int wid = tid >> 5;
    const int row = blockIdx.x * 8 + wid;

    if (tid == 0) oddor = 0;
    __syncthreads();
    {
        const int* t32 = (const int*)target;
        int f = 0;
        for (int i = tid; i < BT / 2; i += 256) f |= t32[2 * i + 1];
        if (f) atomicOr(&oddor, 1);
    }
    __syncthreads();

    float s = 0.f;
    const float* zr = g_zpart + (size_t)row * NZSL;
    for (int t = lane; t < NZSL; t += 32) s += zr[t];
    #pragma unroll
    for (int o = 16; o > 0; o >>= 1)
        s += __shfl_xor_sync(0xFFFFFFFFu, s, o);

    if (lane == 0) {
        out[OUT_LSE + row] = logf(s);
        g_scale[row] = 1.0f / s;
        long long t;
        if (oddor) t = (long long)((const int*)target)[row];
        else       t = ((const long long*)target)[row];
        if (t < 0) t = 0;
        if (t >= VDIM) t = VDIM - 1;
        out[OUT_NTL + row] = -out[OUT_LOGITS + (size_t)row * VDIM + t];
    }
}

__global__ void loss_kernel(float* __restrict__ out)
{
    __shared__ float red[256];
    const int tid = threadIdx.x;
    float s = 0.f;
    for (int i = tid; i < BT; i += 256)
        s += out[OUT_LSE + i] + out[OUT_NTL + i];
    red[tid] = s;
    __syncthreads();
    for (int st = 128; st > 0; st >>= 1) {
        if (tid < st) red[tid] += red[tid + st];
        __syncthreads();
    }
    if (tid == 0) out[OUT_LOSS] = red[0] / (float)BT;
}

// ---------------------------------------------------------------------------
// Phase 3: grad partials = E @ w (K-split x4), direct fragment stores
// ---------------------------------------------------------------------------
__global__ __launch_bounds__(128, 2) void gemm2_kernel()
{
    extern __shared__ uint32_t sm[];
    const uint32_t smb = (uint32_t)__cvta_generic_to_shared(sm);
    GEMM_DECLS
    const int m0 = blockIdx.x * BM;
    const int n0 = blockIdx.y * BN;
    const int s  = blockIdx.z;
    GEMM_ISSUE(g_probs, g_wt2, KC2H)

    const int kbase = s * (VDIM / 32 / SPLIT);    // 250 iters per split
    const int kend  = kbase + (VDIM / 32 / SPLIT);
    issue(kbase); issue(kbase + 1); issue(kbase + 2);
    for (int kt = kbase; kt < kend; kt++) {
        GEMM_WAIT(kt, kend)
        __syncthreads();
        if (kt + 3 < kend) issue(kt + 3);
        GEMM_COMPUTE(kt)
    }

    float* gp = g_gpart + (size_t)s * BT * HDIM;
    #pragma unroll
    for (int mt = 0; mt < 4; mt++) {
        #pragma unroll
        for (int nt = 0; nt < 8; nt++) {
            int r = m0 + wm * 64 + mt * 16 + g;
            int c = n0 + wn * 64 + nt * 8 + tg * 2;
            *(float2*)(gp + (size_t)r * HDIM + c) =
                make_float2(acc[mt][nt][0], acc[mt][nt][1]);
            *(float2*)(gp + (size_t)(r + 8) * HDIM + c) =
                make_float2(acc[mt][nt][2], acc[mt][nt][3]);
        }
    }
}

// ---------------------------------------------------------------------------
// Phase 4: grad_x = (sum_s partial) * 1/Z
// ---------------------------------------------------------------------------
__global__ void gradred_kernel(float* __restrict__ out)
{
    const int row = blockIdx.x;
    const float sc = g_scale[row];
    float* o = out + OUT_GRADX + (size_t)row * HDIM;
    const float* p = g_gpart + (size_t)row * HDIM;
    for (int c = threadIdx.x; c < HDIM; c += 256) {
        float v = p[c];
        #pragma unroll
        for (int s = 1; s < SPLIT; s++)
            v += p[(size_t)s * BT * HDIM + c];
        o[c] = v * sc;
    }
}

// ---------------------------------------------------------------------------
extern "C" void kernel_launch(void* const* d_in, const int* in_sizes, int n_in,
                              void* d_out, int out_size)
{
    const float* x   = (const float*)d_in[0];
    const float* w   = (const float*)d_in[1];
    const void*  tgt = d_in[2];
    float*       out = (float*)d_out;

    cudaFuncSetAttribute(gemm1_kernel,
        cudaFuncAttributeMaxDynamicSharedMemorySize, G_SMEM);
    cudaFuncSetAttribute(gemm2_kernel,
        cudaFuncAttributeMaxDynamicSharedMemorySize, G_SMEM);

    convA_kernel<<<512, 128>>>(x);
    convB_kernel<<<dim3(VDIM / 64, HDIM / 64), 256>>>(w);

    dim3 g1(BT / BM, VDIM / BN);        // (32, 250), m-fastest
    gemm1_kernel<<<g1, 128, G_SMEM>>>(out);

    zred_kernel<<<BT / 8, 256>>>(tgt, out);
    loss_kernel<<<1, 256>>>(out);

    dim3 g2(BT / BM, HDIM / BN, SPLIT); // (32, 16, 4) = 2048 CTAs
    gemm2_kernel<<<g2, 128, G_SMEM>>>();
    gradred_kernel<<<BT, 256>>>(out);
}

// round 16
// speedup vs baseline: 1.0435x; 1.0435x over previous
#include <cuda_runtime.h>
#include <cuda_fp16.h>
#include <cstdint>

#define BT   4096
#define HDIM 2048
#define VDIM 32000
#define KC1H (HDIM / 16)           // 128 k16-chunks (gemm1)
#define KC2H (VDIM / 16)           // 2000 k16-chunks (gemm2)
#define SPLIT 4
#define NZSL 500                   // 250 n-tiles * 2 wn

// Output layout: [loss(1) | logits(BT*V) | lse(BT) | ntl(BT) | grad_x(BT*H)]
#define OUT_LOSS   0
#define OUT_LOGITS 1LL
#define OUT_LSE    (1LL + (long long)BT * VDIM)
#define OUT_NTL    (OUT_LSE + BT)
#define OUT_GRADX  (OUT_NTL + BT)

// Geometry: CTA 128x128, BK=32 (2 k16), 128 thr, 4 warps (2m x 2n), warp 64x64
#define BM 128
#define BN 128
#define STG_AW 2048                // A: 8 m16 * 2 kc * 128 words
#define STG_W  4096                // + B: 8 n16 * 2 kc * 128 words
#define G1_SMEM 67584              // max(4 stages = 65536, sf 128*132*4 = 67584)
#define G2_SMEM 65536              // 4 stages

// ---- scratch (fp16 fragment-major) ----
// A unit [m16][k16]: lane-> uint4 {(g,2tg|+1),(g+8,..),(g,2tg+8|+9),(g+8,..)}
// B unit [n16][k16]: lane-> uint4 {f0.b0, f0.b1, f1.b0, f1.b1}
__device__ uint32_t g_xt   [(size_t)(BT / 16) * KC1H * 128];
__device__ uint32_t g_wt   [(size_t)(VDIM / 16) * KC1H * 128];  // (n=v,k=h)
__device__ uint32_t g_wt2  [(size_t)(HDIM / 16) * KC2H * 128];  // (n=h,k=v)
__device__ uint32_t g_probs[(size_t)(BT / 16) * KC2H * 128];
__device__ float    g_gpart[(size_t)SPLIT * BT * HDIM];
__device__ float    g_zpart[(size_t)BT * NZSL];                 // [row][slice]
__device__ float    g_scale[BT];

__device__ __forceinline__ uint32_t packh2(float lo, float hi) {
    __half2 h = __floats2half2_rn(lo, hi);
    return *(uint32_t*)&h;
}
__device__ __forceinline__ void mma16(float* d, const uint32_t* a, const uint32_t* b) {
    asm volatile(
        "mma.sync.aligned.m16n8k16.row.col.f32.f16.f16.f32 "
        "{%0,%1,%2,%3}, {%4,%5,%6,%7}, {%8,%9}, {%0,%1,%2,%3};\n"
        : "+f"(d[0]), "+f"(d[1]), "+f"(d[2]), "+f"(d[3])
        : "r"(a[0]), "r"(a[1]), "r"(a[2]), "r"(a[3]),
          "r"(b[0]), "r"(b[1]));
}
__device__ __forceinline__ void cpa16(uint32_t smem, const void* gmem) {
    asm volatile("cp.async.cg.shared.global [%0], [%1], 16;\n" :: "r"(smem), "l"(gmem));
}
__device__ __forceinline__ void cpa_commit() {
    asm volatile("cp.async.commit_group;\n" ::: "memory");
}
__device__ __forceinline__ void cpa_wait0() {
    asm volatile("cp.async.wait_group 0;\n" ::: "memory");
}
__device__ __forceinline__ void cpa_wait1() {
    asm volatile("cp.async.wait_group 1;\n" ::: "memory");
}
__device__ __forceinline__ void cpa_wait2() {
    asm volatile("cp.async.wait_group 2;\n" ::: "memory");
}

// ---------------------------------------------------------------------------
// Converters into fp16 fragment-major layouts
// ---------------------------------------------------------------------------
__global__ void convA_kernel(const float* __restrict__ x)
{
    const int lane = threadIdx.x & 31;
    const int g = lane >> 2, tg = lane & 3;
    const int warp = (blockIdx.x * blockDim.x + threadIdx.x) >> 5;
    const int nwarp = (gridDim.x * blockDim.x) >> 5;
    const int NF = (BT / 16) * KC1H;                 // 32768
    for (int f = warp; f < NF; f += nwarp) {
        int m16 = f >> 7, kc = f & (KC1H - 1);
        const float* p = x + (size_t)(m16 * 16 + g) * HDIM + kc * 16;
        uint4 o;
        o.x = packh2(p[2 * tg],            p[2 * tg + 1]);
        o.y = packh2(p[8 * HDIM + 2 * tg], p[8 * HDIM + 2 * tg + 1]);
        o.z = packh2(p[2 * tg + 8],        p[2 * tg + 9]);
        o.w = packh2(p[8 * HDIM + 2 * tg + 8], p[8 * HDIM + 2 * tg + 9]);
        *(uint4*)(g_xt + (size_t)f * 128 + lane * 4) = o;
    }
}
// One pass over w: stage 64x64 tile, emit BOTH g_wt (n16=v,k=h) and g_wt2 (n16=h,k=v)
__global__ void convB_kernel(const float* __restrict__ w)
{
    __shared__ float t[64][68];
    const int v0 = blockIdx.x * 64;      // 500
    const int h0 = blockIdx.y * 64;      // 32
    const int tid = threadIdx.x;         // 256
    #pragma unroll
    for (int i = 0; i < 4; i++) {
        int q = tid + i * 256;           // 1024 float4 chunks
        int r = q >> 4, c4 = q & 15;
        float4 v = *(const float4*)(w + (size_t)(v0 + r) * HDIM + h0 + c4 * 4);
        t[r][c4 * 4 + 0] = v.x; t[r][c4 * 4 + 1] = v.y;
        t[r][c4 * 4 + 2] = v.z; t[r][c4 * 4 + 3] = v.w;
    }
    __syncthreads();
    const int lane = tid & 31, wid = tid >> 5;
    const int g = lane >> 2, tg = lane & 3;
    if (wid < 4) {
        #pragma unroll
        for (int kj = 0; kj < 4; kj++) {
            const float* ra = &t[wid * 16 + g][kj * 16];
            const float* rb = &t[wid * 16 + 8 + g][kj * 16];
            uint4 o;
            o.x = packh2(ra[2 * tg],     ra[2 * tg + 1]);
            o.y = packh2(ra[2 * tg + 8], ra[2 * tg + 9]);
            o.z = packh2(rb[2 * tg],     rb[2 * tg + 1]);
            o.w = packh2(rb[2 * tg + 8], rb[2 * tg + 9]);
            *(uint4*)(g_wt + ((size_t)(v0 / 16 + wid) * KC1H + h0 / 16 + kj) * 128
                      + lane * 4) = o;
        }
    } else {
        const int wp = wid - 4;
        #pragma unroll
        for (int kj = 0; kj < 4; kj++) {
            int vb = kj * 16;
            int ca = wp * 16 + g, cb = wp * 16 + 8 + g;
            uint4 o;
            o.x = packh2(t[vb + 2 * tg][ca],     t[vb + 2 * tg + 1][ca]);
            o.y = packh2(t[vb + 2 * tg + 8][ca], t[vb + 2 * tg + 9][ca]);
            o.z = packh2(t[vb + 2 * tg][cb],     t[vb + 2 * tg + 1][cb]);
            o.w = packh2(t[vb + 2 * tg + 8][cb], t[vb + 2 * tg + 9][cb]);
            *(uint4*)(g_wt2 + ((size_t)(h0 / 16 + wp) * KC2H + v0 / 16 + kj) * 128
                      + lane * 4) = o;
        }
    }
}

// ---------------------------------------------------------------------------
// mainloop pieces: 128x128 CTA, warp 64x64, BK=32 (2 k16), 4-stage, dist-3
// ---------------------------------------------------------------------------
#define GEMM_DECLS                                            \
    const int tid  = threadIdx.x;                             \
    const int lane = tid & 31;                                \
    const int wid  = tid >> 5;                                \
    const int g    = lane >> 2;                               \
    const int tg   = lane & 3;                                \
    const int wm   = wid & 1;                                 \
    const int wn   = wid >> 1;                                \
    float acc[4][8][4];                                       \
    _Pragma("unroll")                                         \
    for (int i = 0; i < 4; i++)                               \
        _Pragma("unroll")                                     \
        for (int j = 0; j < 8; j++)                           \
            _Pragma("unroll")                                 \
            for (int q = 0; q < 4; q++) acc[i][j][q] = 0.f;

#define GEMM_ISSUE(AG, BG, KCD)                                               \
    auto issue = [&](int kt) {                                                \
        const uint32_t sb = smb + (uint32_t)(kt & 3) * (STG_W * 4);           \
        const int kc0 = kt * 2;                                              \
        _Pragma("unroll")                                                     \
        for (int i = 0; i < 4; i++) {             /* A: 512 chunks */         \
            int q = tid + i * 128;                                            \
            int ai = q >> 6, rem = q & 63;                                    \
            int kcl = rem >> 5, c = rem & 31;                                 \
            cpa16(sb + (ai * 256 + kcl * 128 + c * 4) * 4,                    \
                  AG + ((size_t)(m0 / 16 + ai) * KCD + kc0 + kcl) * 128 + c * 4); \
        }                                                                     \
        _Pragma("unroll")                                                     \
        for (int i = 0; i < 4; i++) {             /* B: 512 chunks */         \
            int q = tid + i * 128;                                            \
            int bj = q >> 6, rem = q & 63;                                    \
            int kcl = rem >> 5, c = rem & 31;                                 \
            cpa16(sb + (STG_AW + bj * 256 + kcl * 128 + c * 4) * 4,           \
                  BG + ((size_t)(n0 / 16 + bj) * KCD + kc0 + kcl) * 128 + c * 4); \
        }                                                                     \
        cpa_commit();                                                         \
    };

#define GEMM_COMPUTE(kt)                                                      \
    {                                                                         \
        const uint32_t* Aw = sm + (kt & 3) * STG_W;                           \
        const uint32_t* Bw = Aw + STG_AW;                                     \
        _Pragma("unroll")                                                     \
        for (int kc = 0; kc < 2; kc++) {                                      \
            uint4 av[4];                                                      \
            _Pragma("unroll")                                                 \
            for (int mt = 0; mt < 4; mt++)                                    \
                av[mt] = *(const uint4*)(Aw + (wm * 4 + mt) * 256 + kc * 128 + lane * 4); \
            _Pragma("unroll")                                                 \
            for (int nt16 = 0; nt16 < 4; nt16++) {                            \
                uint4 bv = *(const uint4*)(Bw + (wn * 4 + nt16) * 256 + kc * 128 + lane * 4); \
                _Pragma("unroll")                                             \
                for (int mt = 0; mt < 4; mt++) {                              \
                    mma16(acc[mt][2 * nt16],     (const uint32_t*)&av[mt], &bv.x); \
                    mma16(acc[mt][2 * nt16 + 1], (const uint32_t*)&av[mt], &bv.z); \
                }                                                             \
            }                                                                 \
        }                                                                     \
    }

// pending groups at top of iter kt: {kt .. min(kt+2, kend-1)}
#define GEMM_WAIT(kt, kend)                                   \
    if ((kend) - (kt) >= 3)      cpa_wait2();                 \
    else if ((kend) - (kt) == 2) cpa_wait1();                 \
    else                         cpa_wait0();

// ---------------------------------------------------------------------------
// Phase 1: logits = x @ w^T. Epilogue: z partials + probs from registers,
// logits via smem stage (sector-dense stores).
// ---------------------------------------------------------------------------
__global__ __launch_bounds__(128, 2) void gemm1_kernel(float* __restrict__ out)
{
    extern __shared__ uint32_t sm[];
    const uint32_t smb = (uint32_t)__cvta_generic_to_shared(sm);
    GEMM_DECLS
    const int m0 = blockIdx.x * BM;
    const int n0 = blockIdx.y * BN;
    GEMM_ISSUE(g_xt, g_wt, KC1H)

    issue(0); issue(1); issue(2);
    const int NK = HDIM / 32;   // 64
    for (int kt = 0; kt < NK; kt++) {
        GEMM_WAIT(kt, NK)
        __syncthreads();
        if (kt + 3 < NK) issue(kt + 3);
        GEMM_COMPUTE(kt)
    }

    // ---- z partials straight from fragments ([row][slice] layout) ----
    {
        const int slice = blockIdx.y * 2 + wn;
        #pragma unroll
        for (int mt = 0; mt < 4; mt++) {
            float s0 = 0.f, s1 = 0.f;
            #pragma unroll
            for (int nt = 0; nt < 8; nt++) {
                s0 += __expf(acc[mt][nt][0]) + __expf(acc[mt][nt][1]);
                s1 += __expf(acc[mt][nt][2]) + __expf(acc[mt][nt][3]);
            }
            s0 += __shfl_xor_sync(0xFFFFFFFFu, s0, 1);
            s0 += __shfl_xor_sync(0xFFFFFFFFu, s0, 2);
            s1 += __shfl_xor_sync(0xFFFFFFFFu, s1, 1);
            s1 += __shfl_xor_sync(0xFFFFFFFFu, s1, 2);
            if (tg == 0) {
                int r = m0 + wm * 64 + mt * 16 + g;
                g_zpart[(size_t)r * NZSL + slice]       = s0;
                g_zpart[(size_t)(r + 8) * NZSL + slice] = s1;
            }
        }
    }

    // ---- probs: A-perm units straight from fragments (contiguous uint4) ----
    #pragma unroll
    for (int mt = 0; mt < 4; mt++) {
        #pragma unroll
        for (int j = 0; j < 4; j++) {
            uint4 o;
            o.x = packh2(__expf(acc[mt][2 * j][0]),     __expf(acc[mt][2 * j][1]));
            o.y = packh2(__expf(acc[mt][2 * j][2]),     __expf(acc[mt][2 * j][3]));
            o.z = packh2(__expf(acc[mt][2 * j + 1][0]), __expf(acc[mt][2 * j + 1][1]));
            o.w = packh2(__expf(acc[mt][2 * j + 1][2]), __expf(acc[mt][2 * j + 1][3]));
            *(uint4*)(g_probs + ((size_t)(m0 / 16 + wm * 4 + mt) * KC2H
                                 + (n0 + wn * 64) / 16 + j) * 128 + lane * 4) = o;
        }
    }

    // ---- logits via smem stage (dense coalesced row stores) ----
    __syncthreads();
    float* sf = (float*)sm;                        // [128][132] = 67584 B
    #pragma unroll
    for (int mt = 0; mt < 4; mt++) {
        #pragma unroll
        for (int nt = 0; nt < 8; nt++) {
            int r = wm * 64 + mt * 16 + g;
            int c = wn * 64 + nt * 8 + tg * 2;
            sf[r * 132 + c]           = acc[mt][nt][0];
            sf[r * 132 + c + 1]       = acc[mt][nt][1];
            sf[(r + 8) * 132 + c]     = acc[mt][nt][2];
            sf[(r + 8) * 132 + c + 1] = acc[mt][nt][3];
        }
    }
    __syncthreads();
    float* outL = out + OUT_LOGITS;
    for (int i = 0; i < 128; i++)
        outL[(size_t)(m0 + i) * VDIM + n0 + tid] = sf[i * 132 + tid];
}

// ---------------------------------------------------------------------------
// Phase 2: zred — Z, lse, 1/Z, ntl. Target dtype runtime-detected
// (JAX x64-off downcasts int64 -> int32; odd words all-zero => int64).
// ---------------------------------------------------------------------------
__global__ void zred_kernel(const void* __restrict__ target,
                            float* __restrict__ out)
{
    __shared__ int oddor;
    const int tid = threadIdx.x;
    const int lane = tid & 31;
    const int wid = tid >> 5;
    const int row = blockIdx.x * 8 + wid;

    if (tid == 0) oddor = 0;
    __syncthreads();
    {
        const int* t32 = (const int*)target;
        int f = 0;
        for (int i = tid; i < BT / 2; i += 256) f |= t32[2 * i + 1];
        if (f) atomicOr(&oddor, 1);
    }
    __syncthreads();

    float s = 0.f;
    const float* zr = g_zpart + (size_t)row * NZSL;
    for (int t = lane; t < NZSL; t += 32) s += zr[t];
    #pragma unroll
    for (int o = 16; o > 0; o >>= 1)
        s += __shfl_xor_sync(0xFFFFFFFFu, s, o);

    if (lane == 0) {
        out[OUT_LSE + row] = logf(s);
        g_scale[row] = 1.0f / s;
        long long t;
        if (oddor) t = (long long)((const int*)target)[row];
        else       t = ((const long long*)target)[row];
        if (t < 0) t = 0;
        if (t >= VDIM) t = VDIM - 1;
        out[OUT_NTL + row] = -out[OUT_LOGITS + (size_t)row * VDIM + t];
    }
}

__global__ void loss_kernel(float* __restrict__ out)
{
    __shared__ float red[256];
    const int tid = threadIdx.x;
    float s = 0.f;
    for (int i = tid; i < BT; i += 256)
        s += out[OUT_LSE + i] + out[OUT_NTL + i];
    red[tid] = s;
    __syncthreads();
    for (int st = 128; st > 0; st >>= 1) {
        if (tid < st) red[tid] += red[tid + st];
        __syncthreads();
    }
    if (tid == 0) out[OUT_LOSS] = red[0] / (float)BT;
}

// ---------------------------------------------------------------------------
// Phase 3: grad partials = E @ w (K-split x4), direct fragment stores
// ---------------------------------------------------------------------------
__global__ __launch_bounds__(128, 2) void gemm2_kernel()
{
    extern __shared__ uint32_t sm[];
    const uint32_t smb = (uint32_t)__cvta_generic_to_shared(sm);
    GEMM_DECLS
    const int m0 = blockIdx.x * BM;
    const int n0 = blockIdx.y * BN;
    const int s  = blockIdx.z;
    GEMM_ISSUE(g_probs, g_wt2, KC2H)

    const int kbase = s * (VDIM / 32 / SPLIT);    // 250 iters per split
    const int kend  = kbase + (VDIM / 32 / SPLIT);
    issue(kbase); issue(kbase + 1); issue(kbase + 2);
    for (int kt = kbase; kt < kend; kt++) {
        GEMM_WAIT(kt, kend)
        __syncthreads();
        if (kt + 3 < kend) issue(kt + 3);
        GEMM_COMPUTE(kt)
    }

    float* gp = g_gpart + (size_t)s * BT * HDIM;
    #pragma unroll
    for (int mt = 0; mt < 4; mt++) {
        #pragma unroll
        for (int nt = 0; nt < 8; nt++) {
            int r = m0 + wm * 64 + mt * 16 + g;
            int c = n0 + wn * 64 + nt * 8 + tg * 2;
            *(float2*)(gp + (size_t)r * HDIM + c) =
                make_float2(acc[mt][nt][0], acc[mt][nt][1]);
            *(float2*)(gp + (size_t)(r + 8) * HDIM + c) =
                make_float2(acc[mt][nt][2], acc[mt][nt][3]);
        }
    }
}

// ---------------------------------------------------------------------------
// Phase 4: grad_x = (sum_s partial) * 1/Z
// ---------------------------------------------------------------------------
__global__ void gradred_kernel(float* __restrict__ out)
{
    const int row = blockIdx.x;
    const float sc = g_scale[row];
    float* o = out + OUT_GRADX + (size_t)row * HDIM;
    const float* p = g_gpart + (size_t)row * HDIM;
    for (int c = threadIdx.x; c < HDIM; c += 256) {
        float v = p[c];
        #pragma unroll
        for (int s = 1; s < SPLIT; s++)
            v += p[(size_t)s * BT * HDIM + c];
        o[c] = v * sc;
    }
}

// ---------------------------------------------------------------------------
extern "C" void kernel_launch(void* const* d_in, const int* in_sizes, int n_in,
                              void* d_out, int out_size)
{
    const float* x   = (const float*)d_in[0];
    const float* w   = (const float*)d_in[1];
    const void*  tgt = d_in[2];
    float*       out = (float*)d_out;

    cudaFuncSetAttribute(gemm1_kernel,
        cudaFuncAttributeMaxDynamicSharedMemorySize, G1_SMEM);
    cudaFuncSetAttribute(gemm2_kernel,
        cudaFuncAttributeMaxDynamicSharedMemorySize, G2_SMEM);

    convA_kernel<<<512, 128>>>(x);
    convB_kernel<<<dim3(VDIM / 64, HDIM / 64), 256>>>(w);

    dim3 g1(BT / BM, VDIM / BN);        // (32, 250), m-fastest
    gemm1_kernel<<<g1, 128, G1_SMEM>>>(out);

    zred_kernel<<<BT / 8, 256>>>(tgt, out);
    loss_kernel<<<1, 256>>>(out);

    dim3 g2(BT / BM, HDIM / BN, SPLIT); // (32, 16, 4) = 2048 CTAs
    gemm2_kernel<<<g2, 128, G2_SMEM>>>();
    gradred_kernel<<<BT, 256>>>(out);
}

// round 17
// speedup vs baseline: 1.0439x; 1.0003x over previous
#include <cuda_runtime.h>
#include <cuda_fp16.h>
#include <cstdint>

#define BT   4096
#define HDIM 2048
#define VDIM 32000
#define KC1H (HDIM / 16)           // 128 k16-chunks (gemm1)
#define KC2H (VDIM / 16)           // 2000 k16-chunks (gemm2)
#define SPLIT 4
#define NZSL 500                   // 250 n-tiles * 2 wn

// Output layout: [loss(1) | logits(BT*V) | lse(BT) | ntl(BT) | grad_x(BT*H)]
#define OUT_LOSS   0
#define OUT_LOGITS 1LL
#define OUT_LSE    (1LL + (long long)BT * VDIM)
#define OUT_NTL    (OUT_LSE + BT)
#define OUT_GRADX  (OUT_NTL + BT)

// Geometry: CTA 128x128, BK=32 (2 k16), 128 thr, 4 warps (2m x 2n), warp 64x64
#define BM 128
#define BN 128
#define STG_AW 2048                // A: 8 m16 * 2 kc * 128 words
#define STG_W  4096                // + B: 8 n16 * 2 kc * 128 words
#define G1_SMEM 67584              // max(4 stages = 65536, sf 128*132*4 = 67584)
#define G2_SMEM 65536              // 4 stages

// ---- scratch (fp16 fragment-major) ----
// A unit [m16][k16]: lane-> uint4 {(g,2tg|+1),(g+8,..),(g,2tg+8|+9),(g+8,..)}
// B unit [n16][k16]: lane-> uint4 {f0.b0, f0.b1, f1.b0, f1.b1}
__device__ uint32_t g_xt   [(size_t)(BT / 16) * KC1H * 128];
__device__ uint32_t g_wt   [(size_t)(VDIM / 16) * KC1H * 128];  // (n=v,k=h)
__device__ uint32_t g_wt2  [(size_t)(HDIM / 16) * KC2H * 128];  // (n=h,k=v)
__device__ uint32_t g_probs[(size_t)(BT / 16) * KC2H * 128];
__device__ float    g_gpart[(size_t)SPLIT * BT * HDIM];
__device__ float    g_zpart[(size_t)BT * NZSL];                 // [row][slice]
__device__ float    g_scale[BT];
__device__ int      g_oddor;       // target dtype flag (plain store, no reset needed)

__device__ __forceinline__ uint32_t packh2(float lo, float hi) {
    __half2 h = __floats2half2_rn(lo, hi);
    return *(uint32_t*)&h;
}
__device__ __forceinline__ void mma16(float* d, const uint32_t* a, const uint32_t* b) {
    asm volatile(
        "mma.sync.aligned.m16n8k16.row.col.f32.f16.f16.f32 "
        "{%0,%1,%2,%3}, {%4,%5,%6,%7}, {%8,%9}, {%0,%1,%2,%3};\n"
        : "+f"(d[0]), "+f"(d[1]), "+f"(d[2]), "+f"(d[3])
        : "r"(a[0]), "r"(a[1]), "r"(a[2]), "r"(a[3]),
          "r"(b[0]), "r"(b[1]));
}
__device__ __forceinline__ void cpa16(uint32_t smem, const void* gmem) {
    asm volatile("cp.async.cg.shared.global [%0], [%1], 16;\n" :: "r"(smem), "l"(gmem));
}
__device__ __forceinline__ void cpa_commit() {
    asm volatile("cp.async.commit_group;\n" ::: "memory");
}
__device__ __forceinline__ void cpa_wait0() {
    asm volatile("cp.async.wait_group 0;\n" ::: "memory");
}
__device__ __forceinline__ void cpa_wait1() {
    asm volatile("cp.async.wait_group 1;\n" ::: "memory");
}
__device__ __forceinline__ void cpa_wait2() {
    asm volatile("cp.async.wait_group 2;\n" ::: "memory");
}

// ---------------------------------------------------------------------------
// Converters into fp16 fragment-major layouts
// ---------------------------------------------------------------------------
__global__ void convA_kernel(const float* __restrict__ x,
                             const int* __restrict__ t32)
{
    // block 0: target dtype detection (JAX x64-off downcasts int64 -> int32;
    // odd words all-zero => little-endian int64 with values < 32000)
    if (blockIdx.x == 0) {
        __shared__ int red[128];
        int f = 0;
        for (int i = threadIdx.x; i < BT / 2; i += 128) f |= t32[2 * i + 1];
        red[threadIdx.x] = f;
        __syncthreads();
        for (int s = 64; s > 0; s >>= 1) {
            if (threadIdx.x < s) red[threadIdx.x] |= red[threadIdx.x + s];
            __syncthreads();
        }
        if (threadIdx.x == 0) g_oddor = red[0];
    }

    const int lane = threadIdx.x & 31;
    const int g = lane >> 2, tg = lane & 3;
    const int warp = (blockIdx.x * blockDim.x + threadIdx.x) >> 5;
    const int nwarp = (gridDim.x * blockDim.x) >> 5;
    const int NF = (BT / 16) * KC1H;                 // 32768
    for (int f = warp; f < NF; f += nwarp) {
        int m16 = f >> 7, kc = f & (KC1H - 1);
        const float* p = x + (size_t)(m16 * 16 + g) * HDIM + kc * 16;
        uint4 o;
        o.x = packh2(p[2 * tg],            p[2 * tg + 1]);
        o.y = packh2(p[8 * HDIM + 2 * tg], p[8 * HDIM + 2 * tg + 1]);
        o.z = packh2(p[2 * tg + 8],        p[2 * tg + 9]);
        o.w = packh2(p[8 * HDIM + 2 * tg + 8], p[8 * HDIM + 2 * tg + 9]);
        *(uint4*)(g_xt + (size_t)f * 128 + lane * 4) = o;
    }
}
// One pass over w: stage 64x64 tile, emit BOTH g_wt (n16=v,k=h) and g_wt2 (n16=h,k=v)
__global__ void convB_kernel(const float* __restrict__ w)
{
    __shared__ float t[64][68];
    const int v0 = blockIdx.x * 64;      // 500
    const int h0 = blockIdx.y * 64;      // 32
    const int tid = threadIdx.x;         // 256
    #pragma unroll
    for (int i = 0; i < 4; i++) {
        int q = tid + i * 256;           // 1024 float4 chunks
        int r = q >> 4, c4 = q & 15;
        float4 v = *(const float4*)(w + (size_t)(v0 + r) * HDIM + h0 + c4 * 4);
        t[r][c4 * 4 + 0] = v.x; t[r][c4 * 4 + 1] = v.y;
        t[r][c4 * 4 + 2] = v.z; t[r][c4 * 4 + 3] = v.w;
    }
    __syncthreads();
    const int lane = tid & 31, wid = tid >> 5;
    const int g = lane >> 2, tg = lane & 3;
    if (wid < 4) {
        #pragma unroll
        for (int kj = 0; kj < 4; kj++) {
            const float* ra = &t[wid * 16 + g][kj * 16];
            const float* rb = &t[wid * 16 + 8 + g][kj * 16];
            uint4 o;
            o.x = packh2(ra[2 * tg],     ra[2 * tg + 1]);
            o.y = packh2(ra[2 * tg + 8], ra[2 * tg + 9]);
            o.z = packh2(rb[2 * tg],     rb[2 * tg + 1]);
            o.w = packh2(rb[2 * tg + 8], rb[2 * tg + 9]);
            *(uint4*)(g_wt + ((size_t)(v0 / 16 + wid) * KC1H + h0 / 16 + kj) * 128
                      + lane * 4) = o;
        }
    } else {
        const int wp = wid - 4;
        #pragma unroll
        for (int kj = 0; kj < 4; kj++) {
            int vb = kj * 16;
            int ca = wp * 16 + g, cb = wp * 16 + 8 + g;
            uint4 o;
            o.x = packh2(t[vb + 2 * tg][ca],     t[vb + 2 * tg + 1][ca]);
            o.y = packh2(t[vb + 2 * tg + 8][ca], t[vb + 2 * tg + 9][ca]);
            o.z = packh2(t[vb + 2 * tg][cb],     t[vb + 2 * tg + 1][cb]);
            o.w = packh2(t[vb + 2 * tg + 8][cb], t[vb + 2 * tg + 9][cb]);
            *(uint4*)(g_wt2 + ((size_t)(h0 / 16 + wp) * KC2H + v0 / 16 + kj) * 128
                      + lane * 4) = o;
        }
    }
}

// ---------------------------------------------------------------------------
// mainloop pieces: 128x128 CTA, warp 64x64, BK=32 (2 k16), 4-stage, dist-3
// ---------------------------------------------------------------------------
#define GEMM_DECLS                                            \
    const int tid  = threadIdx.x;                             \
    const int lane = tid & 31;                                \
    const int wid  = tid >> 5;                                \
    const int g    = lane >> 2;                               \
    const int tg   = lane & 3;                                \
    const int wm   = wid & 1;                                 \
    const int wn   = wid >> 1;                                \
    float acc[4][8][4];                                       \
    _Pragma("unroll")                                         \
    for (int i = 0; i < 4; i++)                               \
        _Pragma("unroll")                                     \
        for (int j = 0; j < 8; j++)                           \
            _Pragma("unroll")                                 \
            for (int q = 0; q < 4; q++) acc[i][j][q] = 0.f;

#define GEMM_ISSUE(AG, BG, KCD)                                               \
    auto issue = [&](int kt) {                                                \
        const uint32_t sb = smb + (uint32_t)(kt & 3) * (STG_W * 4);           \
        const int kc0 = kt * 2;                                              \
        _Pragma("unroll")                                                     \
        for (int i = 0; i < 4; i++) {             /* A: 512 chunks */         \
            int q = tid + i * 128;                                            \
            int ai = q >> 6, rem = q & 63;                                    \
            int kcl = rem >> 5, c = rem & 31;                                 \
            cpa16(sb + (ai * 256 + kcl * 128 + c * 4) * 4,                    \
                  AG + ((size_t)(m0 / 16 + ai) * KCD + kc0 + kcl) * 128 + c * 4); \
        }                                                                     \
        _Pragma("unroll")                                                     \
        for (int i = 0; i < 4; i++) {             /* B: 512 chunks */         \
            int q = tid + i * 128;                                            \
            int bj = q >> 6, rem = q & 63;                                    \
            int kcl = rem >> 5, c = rem & 31;                                 \
            cpa16(sb + (STG_AW + bj * 256 + kcl * 128 + c * 4) * 4,           \
                  BG + ((size_t)(n0 / 16 + bj) * KCD + kc0 + kcl) * 128 + c * 4); \
        }                                                                     \
        cpa_commit();                                                         \
    };

#define GEMM_COMPUTE(kt)                                                      \
    {                                                                         \
        const uint32_t* Aw = sm + (kt & 3) * STG_W;                           \
        const uint32_t* Bw = Aw + STG_AW;                                     \
        _Pragma("unroll")                                                     \
        for (int kc = 0; kc < 2; kc++) {                                      \
            uint4 av[4];                                                      \
            _Pragma("unroll")                                                 \
            for (int mt = 0; mt < 4; mt++)                                    \
                av[mt] = *(const uint4*)(Aw + (wm * 4 + mt) * 256 + kc * 128 + lane * 4); \
            _Pragma("unroll")                                                 \
            for (int nt16 = 0; nt16 < 4; nt16++) {                            \
                uint4 bv = *(const uint4*)(Bw + (wn * 4 + nt16) * 256 + kc * 128 + lane * 4); \
                _Pragma("unroll")                                             \
                for (int mt = 0; mt < 4; mt++) {                              \
                    mma16(acc[mt][2 * nt16],     (const uint32_t*)&av[mt], &bv.x); \
                    mma16(acc[mt][2 * nt16 + 1], (const uint32_t*)&av[mt], &bv.z); \
                }                                                             \
            }                                                                 \
        }                                                                     \
    }

// pending groups at top of iter kt: {kt .. min(kt+2, kend-1)}
#define GEMM_WAIT(kt, kend)                                   \
    if ((kend) - (kt) >= 3)      cpa_wait2();                 \
    else if ((kend) - (kt) == 2) cpa_wait1();                 \
    else                         cpa_wait0();

// ---------------------------------------------------------------------------
// Phase 1: logits = x @ w^T. Epilogue: z partials + probs from registers,
// logits via smem stage (sector-dense stores).
// ---------------------------------------------------------------------------
__global__ __launch_bounds__(128, 2) void gemm1_kernel(float* __restrict__ out)
{
    extern __shared__ uint32_t sm[];
    const uint32_t smb = (uint32_t)__cvta_generic_to_shared(sm);
    GEMM_DECLS
    const int m0 = blockIdx.x * BM;
    const int n0 = blockIdx.y * BN;
    GEMM_ISSUE(g_xt, g_wt, KC1H)

    issue(0); issue(1); issue(2);
    const int NK = HDIM / 32;   // 64
    for (int kt = 0; kt < NK; kt++) {
        GEMM_WAIT(kt, NK)
        __syncthreads();
        if (kt + 3 < NK) issue(kt + 3);
        GEMM_COMPUTE(kt)
    }

    // ---- z partials straight from fragments ([row][slice] layout) ----
    {
        const int slice = blockIdx.y * 2 + wn;
        #pragma unroll
        for (int mt = 0; mt < 4; mt++) {
            float s0 = 0.f, s1 = 0.f;
            #pragma unroll
            for (int nt = 0; nt < 8; nt++) {
                s0 += __expf(acc[mt][nt][0]) + __expf(acc[mt][nt][1]);
                s1 += __expf(acc[mt][nt][2]) + __expf(acc[mt][nt][3]);
            }
            s0 += __shfl_xor_sync(0xFFFFFFFFu, s0, 1);
            s0 += __shfl_xor_sync(0xFFFFFFFFu, s0, 2);
            s1 += __shfl_xor_sync(0xFFFFFFFFu, s1, 1);
            s1 += __shfl_xor_sync(0xFFFFFFFFu, s1, 2);
            if (tg == 0) {
                int r = m0 + wm * 64 + mt * 16 + g;
                g_zpart[(size_t)r * NZSL + slice]       = s0;
                g_zpart[(size_t)(r + 8) * NZSL + slice] = s1;
            }
        }
    }

    // ---- probs: A-perm units straight from fragments (contiguous uint4) ----
    #pragma unroll
    for (int mt = 0; mt < 4; mt++) {
        #pragma unroll
        for (int j = 0; j < 4; j++) {
            uint4 o;
            o.x = packh2(__expf(acc[mt][2 * j][0]),     __expf(acc[mt][2 * j][1]));
            o.y = packh2(__expf(acc[mt][2 * j][2]),     __expf(acc[mt][2 * j][3]));
            o.z = packh2(__expf(acc[mt][2 * j + 1][0]), __expf(acc[mt][2 * j + 1][1]));
            o.w = packh2(__expf(acc[mt][2 * j + 1][2]), __expf(acc[mt][2 * j + 1][3]));
            *(uint4*)(g_probs + ((size_t)(m0 / 16 + wm * 4 + mt) * KC2H
                                 + (n0 + wn * 64) / 16 + j) * 128 + lane * 4) = o;
        }
    }

    // ---- logits via smem stage (dense coalesced row stores) ----
    __syncthreads();
    float* sf = (float*)sm;                        // [128][132] = 67584 B
    #pragma unroll
    for (int mt = 0; mt < 4; mt++) {
        #pragma unroll
        for (int nt = 0; nt < 8; nt++) {
            int r = wm * 64 + mt * 16 + g;
            int c = wn * 64 + nt * 8 + tg * 2;
            sf[r * 132 + c]           = acc[mt][nt][0];
            sf[r * 132 + c + 1]       = acc[mt][nt][1];
            sf[(r + 8) * 132 + c]     = acc[mt][nt][2];
            sf[(r + 8) * 132 + c + 1] = acc[mt][nt][3];
        }
    }
    __syncthreads();
    float* outL = out + OUT_LOGITS;
    for (int i = 0; i < 128; i++)
        outL[(size_t)(m0 + i) * VDIM + n0 + tid] = sf[i * 132 + tid];
}

// ---------------------------------------------------------------------------
// Phase 2: zred — Z, lse, 1/Z, ntl (dtype flag precomputed in convA).
// ---------------------------------------------------------------------------
__global__ void zred_kernel(const void* __restrict__ target,
                            float* __restrict__ out)
{
    const int tid = threadIdx.x;
    const int lane = tid & 31;
    const int wid = tid >> 5;
    const int row = blockIdx.x * 8 + wid;

    float s = 0.f;
    const float* zr = g_zpart + (size_t)row * NZSL;
    for (int t = lane; t < NZSL; t += 32) s += zr[t];
    #pragma unroll
    for (int o = 16; o > 0; o >>= 1)
        s += __shfl_xor_sync(0xFFFFFFFFu, s, o);

    if (lane == 0) {
        out[OUT_LSE + row] = logf(s);
        g_scale[row] = 1.0f / s;
        long long t;
        if (g_oddor) t = (long long)((const int*)target)[row];
        else         t = ((const long long*)target)[row];
        if (t < 0) t = 0;
        if (t >= VDIM) t = VDIM - 1;
        out[OUT_NTL + row] = -out[OUT_LOGITS + (size_t)row * VDIM + t];
    }
}

// ---------------------------------------------------------------------------
// Phase 3: grad partials = E @ w (K-split x4), direct fragment stores
// ---------------------------------------------------------------------------
__global__ __launch_bounds__(128, 2) void gemm2_kernel()
{
    extern __shared__ uint32_t sm[];
    const uint32_t smb = (uint32_t)__cvta_generic_to_shared(sm);
    GEMM_DECLS
    const int m0 = blockIdx.x * BM;
    const int n0 = blockIdx.y * BN;
    const int s  = blockIdx.z;
    GEMM_ISSUE(g_probs, g_wt2, KC2H)

    const int kbase = s * (VDIM / 32 / SPLIT);    // 250 iters per split
    const int kend  = kbase + (VDIM / 32 / SPLIT);
    issue(kbase); issue(kbase + 1); issue(kbase + 2);
    for (int kt = kbase; kt < kend; kt++) {
        GEMM_WAIT(kt, kend)
        __syncthreads();
        if (kt + 3 < kend) issue(kt + 3);
        GEMM_COMPUTE(kt)
    }

    float* gp = g_gpart + (size_t)s * BT * HDIM;
    #pragma unroll
    for (int mt = 0; mt < 4; mt++) {
        #pragma unroll
        for (int nt = 0; nt < 8; nt++) {
            int r = m0 + wm * 64 + mt * 16 + g;
            int c = n0 + wn * 64 + nt * 8 + tg * 2;
            *(float2*)(gp + (size_t)r * HDIM + c) =
                make_float2(acc[mt][nt][0], acc[mt][nt][1]);
            *(float2*)(gp + (size_t)(r + 8) * HDIM + c) =
                make_float2(acc[mt][nt][2], acc[mt][nt][3]);
        }
    }
}

// ---------------------------------------------------------------------------
// Phase 4: grad_x = (sum_s partial) * 1/Z ; block BT computes the mean loss.
// ---------------------------------------------------------------------------
__global__ void gradred_kernel(float* __restrict__ out)
{
    const int row = blockIdx.x;
    if (row == BT) {
        __shared__ float red[256];
        const int tid = threadIdx.x;
        float s = 0.f;
        for (int i = tid; i < BT; i += 256)
            s += out[OUT_LSE + i] + out[OUT_NTL + i];
        red[tid] = s;
        __syncthreads();
        for (int st = 128; st > 0; st >>= 1) {
            if (tid < st) red[tid] += red[tid + st];
            __syncthreads();
        }
        if (tid == 0) out[OUT_LOSS] = red[0] / (float)BT;
        return;
    }
    const float sc = g_scale[row];
    float* o = out + OUT_GRADX + (size_t)row * HDIM;
    const float* p = g_gpart + (size_t)row * HDIM;
    for (int c = threadIdx.x; c < HDIM; c += 256) {
        float v = p[c];
        #pragma unroll
        for (int s = 1; s < SPLIT; s++)
            v += p[(size_t)s * BT * HDIM + c];
        o[c] = v * sc;
    }
}

// ---------------------------------------------------------------------------
extern "C" void kernel_launch(void* const* d_in, const int* in_sizes, int n_in,
                              void* d_out, int out_size)
{
    const float* x   = (const float*)d_in[0];
    const float* w   = (const float*)d_in[1];
    const void*  tgt = d_in[2];
    float*       out = (float*)d_out;

    cudaFuncSetAttribute(gemm1_kernel,
        cudaFuncAttributeMaxDynamicSharedMemorySize, G1_SMEM);
    cudaFuncSetAttribute(gemm2_kernel,
        cudaFuncAttributeMaxDynamicSharedMemorySize, G2_SMEM);

    convA_kernel<<<512, 128>>>(x, (const int*)tgt);
    convB_kernel<<<dim3(VDIM / 64, HDIM / 64), 256>>>(w);

    dim3 g1(BT / BM, VDIM / BN);        // (32, 250), m-fastest
    gemm1_kernel<<<g1, 128, G1_SMEM>>>(out);

    zred_kernel<<<BT / 8, 256>>>(tgt, out);

    dim3 g2(BT / BM, HDIM / BN, SPLIT); // (32, 16, 4) = 2048 CTAs
    gemm2_kernel<<<g2, 128, G2_SMEM>>>();
    gradred_kernel<<<BT + 1, 256>>>(out);
}